// round 1
// baseline (speedup 1.0000x reference)
#include <cuda_runtime.h>
#include <cstdint>

#define N    2048
#define DIN  256
#define PROJC 256
#define TM   16
#define SROW 2049           // padded score row stride (bank-conflict-free)
#define VCHUNK 128

// 2 MB scratch for projection output: rows = [Q(64) | K(64) | V(64) | R(64)]
__device__ float g_proj[N * PROJC];

// ---------------------------------------------------------------------------
// Kernel 1: proj = H @ W^T   (2048 x 256) = (2048 x 256) @ (256 x 256)^T
// ---------------------------------------------------------------------------
__global__ __launch_bounds__(256) void proj_kernel(const float* __restrict__ H,
                                                   const float* __restrict__ W,
                                                   float* __restrict__ proj) {
    __shared__ float Hsh[TM][64];
    extern __shared__ float Wsh[];          // [256][65] padded
    const int t  = threadIdx.x;             // output column 0..255
    const int i0 = blockIdx.x * TM;

    float acc[TM];
#pragma unroll
    for (int i = 0; i < TM; i++) acc[i] = 0.f;

    for (int kc = 0; kc < DIN; kc += 64) {
#pragma unroll
        for (int r = 0; r < 4; r++) {
            int idx = t + r * 256;
            Hsh[idx >> 6][idx & 63] = H[(i0 + (idx >> 6)) * DIN + kc + (idx & 63)];
        }
#pragma unroll 8
        for (int r = 0; r < 64; r++) {
            int idx = t + r * 256;
            int cc = idx >> 6, kk = idx & 63;
            Wsh[cc * 65 + kk] = W[cc * DIN + kc + kk];
        }
        __syncthreads();
#pragma unroll
        for (int k = 0; k < 64; k++) {
            float w = Wsh[t * 65 + k];
#pragma unroll
            for (int i = 0; i < TM; i++) acc[i] = fmaf(Hsh[i][k], w, acc[i]);
        }
        __syncthreads();
    }
#pragma unroll
    for (int i = 0; i < TM; i++) proj[(i0 + i) * PROJC + t] = acc[i];
}

// ---------------------------------------------------------------------------
// Packed butterfly: reduces two values with one shfl per level.
// On lanes with (l & mask)==0 the return value carries a's partial,
// on lanes with the bit set it carries b's partial; both get summed
// across the `mask` lane-pairs.
// ---------------------------------------------------------------------------
__device__ __forceinline__ float combine2(float a, float b, int mask, int l) {
    float sel = (l & mask) ? a : b;
    float t = __shfl_xor_sync(0xffffffffu, sel, mask);
    return (l & mask) ? (b + t) : (a + t);
}

// ---------------------------------------------------------------------------
// Kernel 2: fused scores + softmax + attn@V for a 16-row tile.
// 512 threads: warp w handles j = w (mod 16) in the score phase and
// query row (i0+w) in the softmax / AV phases. Lane l owns dims {2l,2l+1}.
// ---------------------------------------------------------------------------
__global__ __launch_bounds__(512, 1) void attn_kernel(const float* __restrict__ D,
                                                      const float* __restrict__ proj,
                                                      float* __restrict__ out) {
    extern __shared__ float smem[];
    float* s   = smem;                       // TM * SROW scores -> probs
    float* Vsh = smem + TM * SROW;           // VCHUNK * 64

    const int t  = threadIdx.x;
    const int w  = t >> 5;                   // warp 0..15
    const int l  = t & 31;
    const int i0 = blockIdx.x * TM;

    const float scale = 0.08838834764831845f;  // 1/sqrt(DK+DR)

    // Per-lane pre-scaled Q,R fragments (dims 2l, 2l+1) for all 16 rows.
    float2 q2[TM], r2[TM];
#pragma unroll
    for (int i = 0; i < TM; i++) {
        const float* row = proj + (size_t)(i0 + i) * PROJC;
        float2 qq = *(const float2*)(row + 2 * l);          // Q: cols 0..63
        float2 rr = *(const float2*)(row + 192 + 2 * l);    // R: cols 192..255
        q2[i] = make_float2(qq.x * scale, qq.y * scale);
        r2[i] = make_float2(rr.x * scale, rr.y * scale);
    }

    // Lane -> score-row permutation of the packed reduction tree.
    const int irow = ((l >> 4) & 1) | (((l >> 3) & 1) << 1) |
                     (((l >> 2) & 1) << 2) | (((l >> 1) & 1) << 3);

    // ---------------- scores: s[i][j] = scale*(Q[i].K[j] + R[i].D[i,j]) -----
    const float* Dp = D + ((size_t)i0 * N + w) * 64 + 2 * l;
    const float* Kp = proj + (size_t)w * PROJC + 64 + 2 * l;   // K: cols 64..127
    int j = w;
    for (int jj = 0; jj < N / 16; jj++) {
        float2 kv = *(const float2*)Kp;
        float v[TM];
#pragma unroll
        for (int i = 0; i < TM; i++) {
            float2 dv = *(const float2*)(Dp + (size_t)i * ((size_t)N * 64));
            v[i] = fmaf(dv.x, r2[i].x,
                   fmaf(dv.y, r2[i].y,
                   fmaf(kv.x, q2[i].x, kv.y * q2[i].y)));
        }
        // 16 simultaneous 32-lane reductions in 16 shfls.
        float c0 = combine2(v[0],  v[1],  16, l);
        float c1 = combine2(v[2],  v[3],  16, l);
        float c2 = combine2(v[4],  v[5],  16, l);
        float c3 = combine2(v[6],  v[7],  16, l);
        float c4 = combine2(v[8],  v[9],  16, l);
        float c5 = combine2(v[10], v[11], 16, l);
        float c6 = combine2(v[12], v[13], 16, l);
        float c7 = combine2(v[14], v[15], 16, l);
        float d0 = combine2(c0, c1, 8, l);
        float d1 = combine2(c2, c3, 8, l);
        float d2 = combine2(c4, c5, 8, l);
        float d3 = combine2(c6, c7, 8, l);
        float e0 = combine2(d0, d1, 4, l);
        float e1 = combine2(d2, d3, 4, l);
        float f  = combine2(e0, e1, 2, l);
        float g  = f + __shfl_xor_sync(0xffffffffu, f, 1);
        if (!(l & 1)) s[irow * SROW + j] = g;   // 16 lanes, distinct banks

        Dp += 16 * 64;
        Kp += 16 * PROJC;
        j  += 16;
    }
    __syncthreads();

    // ---------------- softmax: warp w owns row w ----------------------------
    float* srow = s + w * SROW;
    float m = -1e30f;
    for (int jx = l; jx < N; jx += 32) m = fmaxf(m, srow[jx]);
#pragma unroll
    for (int o = 16; o; o >>= 1) m = fmaxf(m, __shfl_xor_sync(0xffffffffu, m, o));
    float sum = 0.f;
    for (int jx = l; jx < N; jx += 32) {
        float e = __expf(srow[jx] - m);
        srow[jx] = e;
        sum += e;
    }
#pragma unroll
    for (int o = 16; o; o >>= 1) sum += __shfl_xor_sync(0xffffffffu, sum, o);
    const float rinv = 1.0f / sum;

    // ---------------- out[i0+w] = (p @ V) * rinv ----------------------------
    float2 acc = make_float2(0.f, 0.f);
    for (int jc = 0; jc < N; jc += VCHUNK) {
        __syncthreads();
#pragma unroll
        for (int r = 0; r < (VCHUNK * 64) / (512 * 4); r++) {   // 4 float4 each
            int idx  = t + r * 512;
            int jloc = idx >> 4, vq = idx & 15;
            *(float4*)(Vsh + jloc * 64 + vq * 4) =
                *(const float4*)(proj + (size_t)(jc + jloc) * PROJC + 128 + vq * 4);
        }
        __syncthreads();
#pragma unroll 8
        for (int jl = 0; jl < VCHUNK; jl++) {
            float p = srow[jc + jl];                     // broadcast
            float2 vv = *(const float2*)(Vsh + jl * 64 + 2 * l);
            acc.x = fmaf(p, vv.x, acc.x);
            acc.y = fmaf(p, vv.y, acc.y);
        }
    }
    acc.x *= rinv;
    acc.y *= rinv;
    *(float2*)(out + (size_t)(i0 + w) * 64 + 2 * l) = acc;
}

// ---------------------------------------------------------------------------
extern "C" void kernel_launch(void* const* d_in, const int* in_sizes, int n_in,
                              void* d_out, int out_size) {
    const float* H = (const float*)d_in[0];
    const float* D = (const float*)d_in[1];
    const float* W = (const float*)d_in[2];
    float* out = (float*)d_out;

    const int proj_smem = 256 * 65 * 4;                       // 66,560 B
    const int attn_smem = (TM * SROW + VCHUNK * 64) * 4;      // 163,904 B
    cudaFuncSetAttribute(proj_kernel, cudaFuncAttributeMaxDynamicSharedMemorySize, proj_smem);
    cudaFuncSetAttribute(attn_kernel, cudaFuncAttributeMaxDynamicSharedMemorySize, attn_smem);

    void* proj_ptr = nullptr;
    cudaGetSymbolAddress(&proj_ptr, g_proj);
    float* proj = (float*)proj_ptr;

    proj_kernel<<<N / TM, 256, proj_smem>>>(H, W, proj);
    attn_kernel<<<N / TM, 512, attn_smem>>>(D, proj, out);
}